// round 6
// baseline (speedup 1.0000x reference)
#include <cuda_runtime.h>
#include <cuda_bf16.h>
#include <math.h>
#include <stdint.h>

// Problem constants
#define D_MODEL 1024
#define N_HEADS 16
#define D_HEAD  64
#define SEQ     2048
#define BATCH   2
#define NTOK    (BATCH * SEQ)        // 4096
#define TRIPLE  (3 * D_MODEL)        // 3072
#define KP2     2048                 // split-GEMM inner dim: [hi32|lo32] x 32 chunks

// Scratch (allocation-free rule: __device__ globals)
__device__ __nv_bfloat16 g_a [(size_t)NTOK * KP2];        // A'' (x, then ctx)
__device__ __nv_bfloat16 g_wq[(size_t)TRIPLE * KP2];      // W_qkv''^T
__device__ __nv_bfloat16 g_wp[(size_t)D_MODEL * KP2];     // W_proj''^T
__device__ __nv_bfloat16 g_qh[(size_t)NTOK * TRIPLE];     // qkv hi (bf16)
__device__ __nv_bfloat16 g_ql[(size_t)NTOK * TRIPLE];     // qkv lo (bf16)

// ============================ helpers ========================================
__device__ __forceinline__ uint32_t smem_u32(const void* p) {
    uint32_t a;
    asm("{ .reg .u64 t; cvta.to.shared.u64 t, %1; cvt.u32.u64 %0, t; }" : "=r"(a) : "l"(p));
    return a;
}
#define SW128(off) ((off) ^ (((off) >> 3) & 0x70))

__device__ __forceinline__ void cp16(uint32_t dst, const void* src) {
    asm volatile("cp.async.cg.shared.global [%0], [%1], 16;" :: "r"(dst), "l"(src) : "memory");
}
#define CP_COMMIT() asm volatile("cp.async.commit_group;" ::: "memory")
#define CP_WAIT(n)  asm volatile("cp.async.wait_group %0;" :: "n"(n) : "memory")

__device__ __forceinline__ void ldmx4(uint32_t* r, uint32_t addr) {
    asm volatile("ldmatrix.sync.aligned.m8n8.x4.shared.b16 {%0,%1,%2,%3}, [%4];"
                 : "=r"(r[0]), "=r"(r[1]), "=r"(r[2]), "=r"(r[3]) : "r"(addr));
}
__device__ __forceinline__ void ldmx2(uint32_t* r, uint32_t addr) {
    asm volatile("ldmatrix.sync.aligned.m8n8.x2.shared.b16 {%0,%1}, [%2];"
                 : "=r"(r[0]), "=r"(r[1]) : "r"(addr));
}
__device__ __forceinline__ void ldmx2t(uint32_t* r, uint32_t addr) {
    asm volatile("ldmatrix.sync.aligned.m8n8.x2.trans.shared.b16 {%0,%1}, [%2];"
                 : "=r"(r[0]), "=r"(r[1]) : "r"(addr));
}
__device__ __forceinline__ void mma16816(float* d, const uint32_t* a, const uint32_t* b) {
    asm volatile(
        "mma.sync.aligned.m16n8k16.row.col.f32.bf16.bf16.f32 "
        "{%0,%1,%2,%3}, {%4,%5,%6,%7}, {%8,%9}, {%0,%1,%2,%3};"
        : "+f"(d[0]), "+f"(d[1]), "+f"(d[2]), "+f"(d[3])
        : "r"(a[0]), "r"(a[1]), "r"(a[2]), "r"(a[3]), "r"(b[0]), "r"(b[1]));
}
__device__ __forceinline__ uint32_t packbf2(float a, float b) {
    __nv_bfloat162 t = __floats2bfloat162_rn(a, b);
    return *reinterpret_cast<uint32_t*>(&t);
}
__device__ __forceinline__ void store_hilo2(__nv_bfloat16* hi_p, __nv_bfloat16* lo_p,
                                            float a, float b) {
    __nv_bfloat16 ha = __float2bfloat16(a), hb = __float2bfloat16(b);
    __nv_bfloat162 hv; hv.x = ha; hv.y = hb;
    __nv_bfloat162 lv;
    lv.x = __float2bfloat16(a - __bfloat162float(ha));
    lv.y = __float2bfloat16(b - __bfloat162float(hb));
    *reinterpret_cast<__nv_bfloat162*>(hi_p) = hv;
    *reinterpret_cast<__nv_bfloat162*>(lo_p) = lv;
}

// ============================ conversion kernels =============================
__global__ __launch_bounds__(256) void convert_a_kernel(
    const float* __restrict__ src, __nv_bfloat16* __restrict__ dst, int total)
{
    int i = blockIdx.x * blockDim.x + threadIdx.x;
    if (i >= total) return;
    int m = i >> 10, k = i & 1023;
    float x = src[i];
    __nv_bfloat16 hi = __float2bfloat16(x);
    __nv_bfloat16 lo = __float2bfloat16(x - __bfloat162float(hi));
    size_t o = (size_t)m * KP2 + (size_t)((k >> 5) * 64 + (k & 31));
    dst[o] = hi; dst[o + 32] = lo;
}

__global__ __launch_bounds__(256) void convert_w_kernel(
    const float* __restrict__ W, __nv_bfloat16* __restrict__ dst, int N)
{
    __shared__ float tile[32][33];
    int n0 = blockIdx.x * 32, k0 = blockIdx.y * 32;
    int tx = threadIdx.x, ty = threadIdx.y;             // (32, 8)
    #pragma unroll
    for (int j = 0; j < 32; j += 8)
        tile[ty + j][tx] = W[(size_t)(k0 + ty + j) * N + n0 + tx];
    __syncthreads();
    #pragma unroll
    for (int j = 0; j < 32; j += 8) {
        int n = n0 + ty + j, k = k0 + tx;
        float x = tile[tx][ty + j];
        __nv_bfloat16 hi = __float2bfloat16(x);
        __nv_bfloat16 lo = __float2bfloat16(x - __bfloat162float(hi));
        size_t o = (size_t)n * KP2 + (size_t)((k >> 5) * 64 + (k & 31));
        dst[o] = hi; dst[o + 32] = lo;
    }
}

// ============================ HMMA bf16 GEMM =================================
#define NSTAGES 3
#define NCHUNK2 32
#define STAGE_BYTES 32768
#define GEMM_SMEM (NSTAGES * STAGE_BYTES)

template<int MODE>
__global__ __launch_bounds__(256, 2) void gemm_hmma_kernel(
    const __nv_bfloat16* __restrict__ A, const __nv_bfloat16* __restrict__ B,
    const float* __restrict__ bias, float* __restrict__ C,
    __nv_bfloat16* __restrict__ Chi, __nv_bfloat16* __restrict__ Clo, int N)
{
    extern __shared__ char smem[];
    const uint32_t sb = smem_u32(smem);
    const int tid  = threadIdx.x;
    const int wid  = tid >> 5;
    const int lane = tid & 31;
    const int wm   = wid & 1;
    const int wn   = wid >> 1;
    const int m0   = blockIdx.y * 128;
    const int n0   = blockIdx.x * 128;

    float acc[4][4][4];
    #pragma unroll
    for (int i = 0; i < 4; ++i)
        #pragma unroll
        for (int j = 0; j < 4; ++j)
            #pragma unroll
            for (int r = 0; r < 4; ++r) acc[i][j][r] = 0.f;

    const __nv_bfloat16* Ab = A + (size_t)m0 * KP2;
    const __nv_bfloat16* Bb = B + (size_t)n0 * KP2;

    auto load_chunk = [&](int c) {
        int s = c % NSTAGES;
        uint32_t sa = sb + s * STAGE_BYTES;
        uint32_t sB = sa + 16384;
        size_t koff = (size_t)c * 64;
        #pragma unroll
        for (int t = 0; t < 4; ++t) {
            int id = tid + t * 256;
            int r = id >> 3, c16 = id & 7;
            uint32_t soff = SW128(r * 128 + c16 * 16);
            cp16(sa + soff, Ab + (size_t)r * KP2 + koff + c16 * 8);
            cp16(sB + soff, Bb + (size_t)r * KP2 + koff + c16 * 8);
        }
        CP_COMMIT();
    };

    const int a_row = wm * 64 + (lane & 15);
    const int a_kb  = (lane >> 4) * 16;
    const int b_row = wn * 32 + (lane & 7);
    const int b_kb  = ((lane >> 3) & 1) * 16;

    load_chunk(0);
    load_chunk(1);

    for (int c = 0; c < NCHUNK2; ++c) {
        if (c == NCHUNK2 - 1) { CP_WAIT(0); } else { CP_WAIT(1); }
        __syncthreads();
        if (c + 2 < NCHUNK2) load_chunk(c + 2);

        int s = c % NSTAGES;
        uint32_t sa = sb + s * STAGE_BYTES;
        uint32_t sB = sa + 16384;

        #pragma unroll
        for (int j = 0; j < 2; ++j) {          // k16 group within chunk
            uint32_t ahf[4][4], alf[4][4];
            #pragma unroll
            for (int mt = 0; mt < 4; ++mt) {
                uint32_t base = (uint32_t)((a_row + mt * 16) * 128 + j * 32 + a_kb);
                ldmx4(ahf[mt], sa + SW128(base));
                ldmx4(alf[mt], sa + SW128(base + 64));
            }
            #pragma unroll
            for (int nt = 0; nt < 4; ++nt) {
                uint32_t bh[2], bl[2];
                uint32_t base = (uint32_t)((b_row + nt * 8) * 128 + j * 32 + b_kb);
                ldmx2(bh, sB + SW128(base));
                ldmx2(bl, sB + SW128(base + 64));
                // term-major issue: same-accumulator distance = 4 MMAs
                #pragma unroll
                for (int mt = 0; mt < 4; ++mt) mma16816(acc[mt][nt], ahf[mt], bh);
                #pragma unroll
                for (int mt = 0; mt < 4; ++mt) mma16816(acc[mt][nt], alf[mt], bh);
                #pragma unroll
                for (int mt = 0; mt < 4; ++mt) mma16816(acc[mt][nt], ahf[mt], bl);
            }
        }
    }

    const int er = lane >> 2;
    const int ec = (lane & 3) * 2;
    #pragma unroll
    for (int mt = 0; mt < 4; ++mt) {
        #pragma unroll
        for (int nt = 0; nt < 4; ++nt) {
            int col = n0 + wn * 32 + nt * 8 + ec;
            float bx = bias[col], by = bias[col + 1];
            size_t r0 = (size_t)(m0 + wm * 64 + mt * 16 + er);
            float v00 = acc[mt][nt][0] + bx, v01 = acc[mt][nt][1] + by;
            float v10 = acc[mt][nt][2] + bx, v11 = acc[mt][nt][3] + by;
            if (MODE == 0) {
                float2 a0 = { v00, v01 }, a1 = { v10, v11 };
                *(float2*)&C[r0 * N + col]       = a0;
                *(float2*)&C[(r0 + 8) * N + col] = a1;
            } else {
                store_hilo2(&Chi[r0 * N + col], &Clo[r0 * N + col], v00, v01);
                store_hilo2(&Chi[(r0 + 8) * N + col], &Clo[(r0 + 8) * N + col], v10, v11);
            }
        }
    }
}

// ============================ HMMA flash attention (split-KV warps) ==========
#define ABQ 128
#define ABK 64
#define ATTN_SMEM (32768 + 2 * 32768)
#define OB_STRIDE 66
#define MS_OFF (128 * OB_STRIDE)
#define LS_OFF (MS_OFF + 128)

__global__ __launch_bounds__(256, 1) void attn_hmma_kernel(
    const __nv_bfloat16* __restrict__ qkh, const __nv_bfloat16* __restrict__ qkl,
    __nv_bfloat16* __restrict__ ctxA)
{
    extern __shared__ char smem[];
    const uint32_t sb = smem_u32(smem);
    const uint32_t QH = 0, QL = 16384, STG = 32768;

    const int tid = threadIdx.x, wid = tid >> 5, lane = tid & 31;
    const int wq = wid >> 1;
    const int wk = wid & 1;
    const int qt = (int)gridDim.x - 1 - (int)blockIdx.x;
    const int h = blockIdx.y, b = blockIdx.z;
    const int q0 = qt * ABQ;
    const size_t rowbase = (size_t)b * SEQ;
    const int qcol = h * 64, kcol = 1024 + h * 64, vcol = 2048 + h * 64;

    #pragma unroll
    for (int t = 0; t < 4; ++t) {
        int id = tid + t * 256;
        int r = id >> 3, c = id & 7;
        uint32_t so = SW128(r * 128 + c * 16);
        size_t grow = (rowbase + q0 + r) * TRIPLE + qcol + c * 8;
        cp16(sb + QH + so, qkh + grow);
        cp16(sb + QL + so, qkl + grow);
    }
    CP_COMMIT();

    const int T = (q0 + ABQ) / ABK;

    auto load_kv = [&](int t) {
        uint32_t st = sb + STG + (uint32_t)(t & 1) * 32768;
        int k0 = t * ABK;
        #pragma unroll
        for (int i = 0; i < 2; ++i) {
            int id = tid + i * 256;
            int r = id >> 3, c = id & 7;
            uint32_t so = SW128(r * 128 + c * 16);
            size_t grow = (rowbase + k0 + r) * TRIPLE;
            cp16(st + 0     + so, qkh + grow + kcol + c * 8);
            cp16(st + 8192  + so, qkl + grow + kcol + c * 8);
            cp16(st + 16384 + so, qkh + grow + vcol + c * 8);
            cp16(st + 24576 + so, qkl + grow + vcol + c * 8);
        }
        CP_COMMIT();
    };
    load_kv(0);
    CP_WAIT(0);
    __syncthreads();

    uint32_t qhf[2][4][4], qlf[2][4][4];
    {
        int arow = wq * 32 + (lane & 15);
        int akb = (lane >> 4) * 16;
        #pragma unroll
        for (int mt = 0; mt < 2; ++mt)
            #pragma unroll
            for (int ks = 0; ks < 4; ++ks) {
                uint32_t off = (uint32_t)((arow + mt * 16) * 128 + ks * 32 + akb);
                ldmx4(qhf[mt][ks], sb + QH + SW128(off));
                ldmx4(qlf[mt][ks], sb + QL + SW128(off));
            }
    }

    // m init = 0: fully-masked first chunk (upper-KV warp) -> p = exp(-1.25e8) = 0
    float m_run[2][2] = {{0.f, 0.f}, {0.f, 0.f}};
    float l_run[2][2] = {{0.f, 0.f}, {0.f, 0.f}};
    float o_acc[2][8][4];
    #pragma unroll
    for (int mt = 0; mt < 2; ++mt)
        #pragma unroll
        for (int nt = 0; nt < 8; ++nt)
            #pragma unroll
            for (int r = 0; r < 4; ++r) o_acc[mt][nt][r] = 0.f;

    const int r0l = lane >> 2;
    const int ecol = (lane & 3) * 2;
    const int brow = lane & 7;
    const int bkb  = ((lane >> 3) & 1) * 16;
    const int vrow = lane & 15;

    for (int t = 0; t < T; ++t) {
        __syncthreads();
        if (t + 1 < T) { load_kv(t + 1); CP_WAIT(1); } else { CP_WAIT(0); }
        __syncthreads();

        uint32_t st = sb + STG + (uint32_t)(t & 1) * 32768;

        // ---- S = Q K^T on this warp's KV half (term-major, nt pairs) ----
        float s_acc[2][4][4];
        #pragma unroll
        for (int mt = 0; mt < 2; ++mt)
            #pragma unroll
            for (int nt = 0; nt < 4; ++nt)
                #pragma unroll
                for (int r = 0; r < 4; ++r) s_acc[mt][nt][r] = 0.f;

        #pragma unroll
        for (int ks = 0; ks < 4; ++ks) {
            #pragma unroll
            for (int np = 0; np < 2; ++np) {
                uint32_t khf[2][2], klf[2][2];
                #pragma unroll
                for (int q = 0; q < 2; ++q) {
                    int nt = np * 2 + q;
                    uint32_t off = (uint32_t)((wk * 32 + nt * 8 + brow) * 128 + ks * 32 + bkb);
                    ldmx2(khf[q], st + 0 + SW128(off));
                    ldmx2(klf[q], st + 8192 + SW128(off));
                }
                #pragma unroll
                for (int q = 0; q < 2; ++q)
                    #pragma unroll
                    for (int mt = 0; mt < 2; ++mt)
                        mma16816(s_acc[mt][np * 2 + q], qhf[mt][ks], khf[q]);
                #pragma unroll
                for (int q = 0; q < 2; ++q)
                    #pragma unroll
                    for (int mt = 0; mt < 2; ++mt)
                        mma16816(s_acc[mt][np * 2 + q], qlf[mt][ks], khf[q]);
                #pragma unroll
                for (int q = 0; q < 2; ++q)
                    #pragma unroll
                    for (int mt = 0; mt < 2; ++mt)
                        mma16816(s_acc[mt][np * 2 + q], qhf[mt][ks], klf[q]);
            }
        }

        // ---- mask (before scale) + scale + running max ----
        const int kb0 = t * ABK + wk * 32;
        float rmax[2][2] = {{-3.0e38f, -3.0e38f}, {-3.0e38f, -3.0e38f}};
        #pragma unroll
        for (int mt = 0; mt < 2; ++mt) {
            int qr0 = q0 + wq * 32 + mt * 16 + r0l;
            int qr1 = qr0 + 8;
            #pragma unroll
            for (int nt = 0; nt < 4; ++nt) {
                int kc = kb0 + nt * 8 + ecol;
                float v0 = (kc     > qr0) ? -1e9f : s_acc[mt][nt][0];
                float v1 = (kc + 1 > qr0) ? -1e9f : s_acc[mt][nt][1];
                float v2 = (kc     > qr1) ? -1e9f : s_acc[mt][nt][2];
                float v3 = (kc + 1 > qr1) ? -1e9f : s_acc[mt][nt][3];
                v0 *= 0.125f; v1 *= 0.125f; v2 *= 0.125f; v3 *= 0.125f;
                s_acc[mt][nt][0] = v0; s_acc[mt][nt][1] = v1;
                s_acc[mt][nt][2] = v2; s_acc[mt][nt][3] = v3;
                rmax[mt][0] = fmaxf(rmax[mt][0], fmaxf(v0, v1));
                rmax[mt][1] = fmaxf(rmax[mt][1], fmaxf(v2, v3));
            }
            #pragma unroll
            for (int off = 1; off <= 2; off <<= 1) {
                rmax[mt][0] = fmaxf(rmax[mt][0], __shfl_xor_sync(0xffffffffu, rmax[mt][0], off));
                rmax[mt][1] = fmaxf(rmax[mt][1], __shfl_xor_sync(0xffffffffu, rmax[mt][1], off));
            }
        }

        float mn[2][2], cr[2][2], ps[2][2];
        #pragma unroll
        for (int mt = 0; mt < 2; ++mt)
            #pragma unroll
            for (int hf = 0; hf < 2; ++hf) {
                mn[mt][hf] = fmaxf(m_run[mt][hf], rmax[mt][hf]);
                cr[mt][hf] = __expf(m_run[mt][hf] - mn[mt][hf]);
                ps[mt][hf] = 0.f;
            }

        uint32_t pha[2][2][4], pla[2][2][4];
        #pragma unroll
        for (int mt = 0; mt < 2; ++mt) {
            #pragma unroll
            for (int j = 0; j < 2; ++j) {
                float p00 = __expf(s_acc[mt][2*j][0] - mn[mt][0]);
                float p01 = __expf(s_acc[mt][2*j][1] - mn[mt][0]);
                float p02 = __expf(s_acc[mt][2*j][2] - mn[mt][1]);
                float p03 = __expf(s_acc[mt][2*j][3] - mn[mt][1]);
                float p10 = __expf(s_acc[mt][2*j+1][0] - mn[mt][0]);
                float p11 = __expf(s_acc[mt][2*j+1][1] - mn[mt][0]);
                float p12 = __expf(s_acc[mt][2*j+1][2] - mn[mt][1]);
                float p13 = __expf(s_acc[mt][2*j+1][3] - mn[mt][1]);
                ps[mt][0] += p00 + p01 + p10 + p11;
                ps[mt][1] += p02 + p03 + p12 + p13;
                __nv_bfloat16 h00 = __float2bfloat16(p00), h01 = __float2bfloat16(p01);
                __nv_bfloat16 h02 = __float2bfloat16(p02), h03 = __float2bfloat16(p03);
                __nv_bfloat16 h10 = __float2bfloat16(p10), h11 = __float2bfloat16(p11);
                __nv_bfloat16 h12 = __float2bfloat16(p12), h13 = __float2bfloat16(p13);
                pha[mt][j][0] = packbf2(__bfloat162float(h00), __bfloat162float(h01));
                pha[mt][j][1] = packbf2(__bfloat162float(h02), __bfloat162float(h03));
                pha[mt][j][2] = packbf2(__bfloat162float(h10), __bfloat162float(h11));
                pha[mt][j][3] = packbf2(__bfloat162float(h12), __bfloat162float(h13));
                pla[mt][j][0] = packbf2(p00 - __bfloat162float(h00), p01 - __bfloat162float(h01));
                pla[mt][j][1] = packbf2(p02 - __bfloat162float(h02), p03 - __bfloat162float(h03));
                pla[mt][j][2] = packbf2(p10 - __bfloat162float(h10), p11 - __bfloat162float(h11));
                pla[mt][j][3] = packbf2(p12 - __bfloat162float(h12), p13 - __bfloat162float(h13));
            }
        }
        #pragma unroll
        for (int mt = 0; mt < 2; ++mt)
            #pragma unroll
            for (int off = 1; off <= 2; off <<= 1) {
                ps[mt][0] += __shfl_xor_sync(0xffffffffu, ps[mt][0], off);
                ps[mt][1] += __shfl_xor_sync(0xffffffffu, ps[mt][1], off);
            }
        #pragma unroll
        for (int mt = 0; mt < 2; ++mt)
            #pragma unroll
            for (int hf = 0; hf < 2; ++hf) {
                l_run[mt][hf] = l_run[mt][hf] * cr[mt][hf] + ps[mt][hf];
                m_run[mt][hf] = mn[mt][hf];
            }
        #pragma unroll
        for (int mt = 0; mt < 2; ++mt)
            #pragma unroll
            for (int nt = 0; nt < 8; ++nt) {
                o_acc[mt][nt][0] *= cr[mt][0]; o_acc[mt][nt][1] *= cr[mt][0];
                o_acc[mt][nt][2] *= cr[mt][1]; o_acc[mt][nt][3] *= cr[mt][1];
            }

        // ---- O += P V on this warp's KV half (term-major, nt pairs) ----
        #pragma unroll
        for (int j = 0; j < 2; ++j) {
            #pragma unroll
            for (int np = 0; np < 4; ++np) {
                uint32_t vhf[2][2], vlf[2][2];
                #pragma unroll
                for (int q = 0; q < 2; ++q) {
                    int nt = np * 2 + q;
                    uint32_t off = (uint32_t)((wk * 32 + j * 16 + vrow) * 128 + nt * 16);
                    ldmx2t(vhf[q], st + 16384 + SW128(off));
                    ldmx2t(vlf[q], st + 24576 + SW128(off));
                }
                #pragma unroll
                for (int q = 0; q < 2; ++q)
                    #pragma unroll
                    for (int mt = 0; mt < 2; ++mt)
                        mma16816(o_acc[mt][np * 2 + q], pha[mt][j], vhf[q]);
                #pragma unroll
                for (int q = 0; q < 2; ++q)
                    #pragma unroll
                    for (int mt = 0; mt < 2; ++mt)
                        mma16816(o_acc[mt][np * 2 + q], pla[mt][j], vhf[q]);
                #pragma unroll
                for (int q = 0; q < 2; ++q)
                    #pragma unroll
                    for (int mt = 0; mt < 2; ++mt)
                        mma16816(o_acc[mt][np * 2 + q], pha[mt][j], vlf[q]);
            }
        }
    }

    // ---- cross-warp merge (wk=1 -> smem, wk=0 merges + writes) ----
    float* smf = reinterpret_cast<float*>(smem);
    __syncthreads();
    if (wk == 1) {
        #pragma unroll
        for (int mt = 0; mt < 2; ++mt) {
            int rA = wq * 32 + mt * 16 + r0l;
            #pragma unroll
            for (int nt = 0; nt < 8; ++nt) {
                int d = nt * 8 + ecol;
                smf[rA * OB_STRIDE + d]     = o_acc[mt][nt][0];
                smf[rA * OB_STRIDE + d + 1] = o_acc[mt][nt][1];
                smf[(rA + 8) * OB_STRIDE + d]     = o_acc[mt][nt][2];
                smf[(rA + 8) * OB_STRIDE + d + 1] = o_acc[mt][nt][3];
            }
            if ((lane & 3) == 0) {
                smf[MS_OFF + rA]     = m_run[mt][0];
                smf[LS_OFF + rA]     = l_run[mt][0];
                smf[MS_OFF + rA + 8] = m_run[mt][1];
                smf[LS_OFF + rA + 8] = l_run[mt][1];
            }
        }
    }
    __syncthreads();
    if (wk == 0) {
        #pragma unroll
        for (int mt = 0; mt < 2; ++mt) {
            int rA = wq * 32 + mt * 16 + r0l;
            float m1a = smf[MS_OFF + rA],     l1a = smf[LS_OFF + rA];
            float m1b = smf[MS_OFF + rA + 8], l1b = smf[LS_OFF + rA + 8];
            float mA = fmaxf(m_run[mt][0], m1a);
            float c0a = __expf(m_run[mt][0] - mA), c1a = __expf(m1a - mA);
            float invA = 1.0f / (l_run[mt][0] * c0a + l1a * c1a);
            float mB = fmaxf(m_run[mt][1], m1b);
            float c0b = __expf(m_run[mt][1] - mB), c1b = __expf(m1b - mB);
            float invB = 1.0f / (l_run[mt][1] * c0b + l1b * c1b);
            size_t tokA = rowbase + (size_t)q0 + rA;
            #pragma unroll
            for (int nt = 0; nt < 8; ++nt) {
                int d = nt * 8 + ecol;
                float vA0 = (o_acc[mt][nt][0] * c0a + smf[rA * OB_STRIDE + d]     * c1a) * invA;
                float vA1 = (o_acc[mt][nt][1] * c0a + smf[rA * OB_STRIDE + d + 1] * c1a) * invA;
                float vB0 = (o_acc[mt][nt][2] * c0b + smf[(rA + 8) * OB_STRIDE + d]     * c1b) * invB;
                float vB1 = (o_acc[mt][nt][3] * c0b + smf[(rA + 8) * OB_STRIDE + d + 1] * c1b) * invB;
                int dg = h * 64 + d;
                size_t colhi = (size_t)((dg >> 5) * 64 + (dg & 31));
                __nv_bfloat16 hA0 = __float2bfloat16(vA0), hA1 = __float2bfloat16(vA1);
                __nv_bfloat16 hB0 = __float2bfloat16(vB0), hB1 = __float2bfloat16(vB1);
                __nv_bfloat162 hvA; hvA.x = hA0; hvA.y = hA1;
                __nv_bfloat162 hvB; hvB.x = hB0; hvB.y = hB1;
                __nv_bfloat162 lvA; lvA.x = __float2bfloat16(vA0 - __bfloat162float(hA0));
                                    lvA.y = __float2bfloat16(vA1 - __bfloat162float(hA1));
                __nv_bfloat162 lvB; lvB.x = __float2bfloat16(vB0 - __bfloat162float(hB0));
                                    lvB.y = __float2bfloat16(vB1 - __bfloat162float(hB1));
                *reinterpret_cast<__nv_bfloat162*>(&ctxA[tokA * KP2 + colhi])            = hvA;
                *reinterpret_cast<__nv_bfloat162*>(&ctxA[tokA * KP2 + colhi + 32])       = lvA;
                *reinterpret_cast<__nv_bfloat162*>(&ctxA[(tokA + 8) * KP2 + colhi])      = hvB;
                *reinterpret_cast<__nv_bfloat162*>(&ctxA[(tokA + 8) * KP2 + colhi + 32]) = lvB;
            }
        }
    }
}

// ============================ launch =========================================
extern "C" void kernel_launch(void* const* d_in, const int* in_sizes, int n_in,
                              void* d_out, int out_size)
{
    (void)in_sizes; (void)n_in; (void)out_size;
    const float* x      = (const float*)d_in[0];
    const float* W_qkv  = (const float*)d_in[1];
    const float* b_qkv  = (const float*)d_in[2];
    const float* W_proj = (const float*)d_in[3];
    const float* b_proj = (const float*)d_in[4];
    float* out = (float*)d_out;

    __nv_bfloat16 *a_buf, *wq_buf, *wp_buf, *qh_buf, *ql_buf;
    cudaGetSymbolAddress((void**)&a_buf, g_a);
    cudaGetSymbolAddress((void**)&wq_buf, g_wq);
    cudaGetSymbolAddress((void**)&wp_buf, g_wp);
    cudaGetSymbolAddress((void**)&qh_buf, g_qh);
    cudaGetSymbolAddress((void**)&ql_buf, g_ql);

    static bool attr_set = false;
    if (!attr_set) {
        cudaFuncSetAttribute(gemm_hmma_kernel<0>, cudaFuncAttributeMaxDynamicSharedMemorySize, GEMM_SMEM);
        cudaFuncSetAttribute(gemm_hmma_kernel<1>, cudaFuncAttributeMaxDynamicSharedMemorySize, GEMM_SMEM);
        cudaFuncSetAttribute(attn_hmma_kernel, cudaFuncAttributeMaxDynamicSharedMemorySize, ATTN_SMEM);
        attr_set = true;
    }

    convert_a_kernel<<<(NTOK * D_MODEL + 255) / 256, 256>>>(x, a_buf, NTOK * D_MODEL);
    {
        dim3 grid(TRIPLE / 32, D_MODEL / 32);
        convert_w_kernel<<<grid, dim3(32, 8)>>>(W_qkv, wq_buf, TRIPLE);
    }
    {
        dim3 grid(D_MODEL / 32, D_MODEL / 32);
        convert_w_kernel<<<grid, dim3(32, 8)>>>(W_proj, wp_buf, D_MODEL);
    }

    {
        dim3 grid(TRIPLE / 128, NTOK / 128);
        gemm_hmma_kernel<1><<<grid, 256, GEMM_SMEM>>>(a_buf, wq_buf, b_qkv, nullptr, qh_buf, ql_buf, TRIPLE);
    }

    {
        dim3 grid(SEQ / ABQ, N_HEADS, BATCH);
        attn_hmma_kernel<<<grid, 256, ATTN_SMEM>>>(qh_buf, ql_buf, a_buf);
    }

    {
        dim3 grid(D_MODEL / 128, NTOK / 128);
        gemm_hmma_kernel<0><<<grid, 256, GEMM_SMEM>>>(a_buf, wp_buf, b_proj, out, nullptr, nullptr, D_MODEL);
    }
}

// round 7
// speedup vs baseline: 1.3382x; 1.3382x over previous
#include <cuda_runtime.h>
#include <cuda_fp16.h>
#include <math.h>
#include <stdint.h>

// Problem constants
#define D_MODEL 1024
#define N_HEADS 16
#define D_HEAD  64
#define SEQ     2048
#define BATCH   2
#define NTOK    (BATCH * SEQ)        // 4096
#define TRIPLE  (3 * D_MODEL)        // 3072
#define KP2     2048                 // A'' inner dim: [hi32|lo32] x 32 chunks (fp16)

// Scratch (allocation-free rule: __device__ globals)
__device__ __half g_a [(size_t)NTOK * KP2];        // A'' (x, then ctx) fp16 hi/lo
__device__ __half g_wq[(size_t)TRIPLE * D_MODEL];  // W_qkv^T fp16 (hi only)
__device__ __half g_wp[(size_t)D_MODEL * D_MODEL]; // W_proj^T fp16 (hi only)
__device__ __half g_qh[(size_t)NTOK * TRIPLE];     // qkv hi (fp16)
__device__ __half g_ql[(size_t)NTOK * TRIPLE];     // qkv lo (fp16)

// ============================ helpers ========================================
__device__ __forceinline__ uint32_t smem_u32(const void* p) {
    uint32_t a;
    asm("{ .reg .u64 t; cvta.to.shared.u64 t, %1; cvt.u32.u64 %0, t; }" : "=r"(a) : "l"(p));
    return a;
}
#define SW128(off) ((off) ^ (((off) >> 3) & 0x70))
#define SW64(off)  ((off) ^ (((off) >> 3) & 0x30))

__device__ __forceinline__ void cp16(uint32_t dst, const void* src) {
    asm volatile("cp.async.cg.shared.global [%0], [%1], 16;" :: "r"(dst), "l"(src) : "memory");
}
#define CP_COMMIT() asm volatile("cp.async.commit_group;" ::: "memory")
#define CP_WAIT(n)  asm volatile("cp.async.wait_group %0;" :: "n"(n) : "memory")

__device__ __forceinline__ void ldmx4(uint32_t* r, uint32_t addr) {
    asm volatile("ldmatrix.sync.aligned.m8n8.x4.shared.b16 {%0,%1,%2,%3}, [%4];"
                 : "=r"(r[0]), "=r"(r[1]), "=r"(r[2]), "=r"(r[3]) : "r"(addr));
}
__device__ __forceinline__ void ldmx2(uint32_t* r, uint32_t addr) {
    asm volatile("ldmatrix.sync.aligned.m8n8.x2.shared.b16 {%0,%1}, [%2];"
                 : "=r"(r[0]), "=r"(r[1]) : "r"(addr));
}
__device__ __forceinline__ void ldmx2t(uint32_t* r, uint32_t addr) {
    asm volatile("ldmatrix.sync.aligned.m8n8.x2.trans.shared.b16 {%0,%1}, [%2];"
                 : "=r"(r[0]), "=r"(r[1]) : "r"(addr));
}
__device__ __forceinline__ void mma16816(float* d, const uint32_t* a, const uint32_t* b) {
    asm volatile(
        "mma.sync.aligned.m16n8k16.row.col.f32.f16.f16.f32 "
        "{%0,%1,%2,%3}, {%4,%5,%6,%7}, {%8,%9}, {%0,%1,%2,%3};"
        : "+f"(d[0]), "+f"(d[1]), "+f"(d[2]), "+f"(d[3])
        : "r"(a[0]), "r"(a[1]), "r"(a[2]), "r"(a[3]), "r"(b[0]), "r"(b[1]));
}
__device__ __forceinline__ uint32_t packh2(float a, float b) {
    __half2 t = __floats2half2_rn(a, b);
    return *reinterpret_cast<uint32_t*>(&t);
}
__device__ __forceinline__ void store_hilo2h(__half* hi_p, __half* lo_p, float a, float b) {
    __half ha = __float2half_rn(a), hb = __float2half_rn(b);
    __half2 hv; hv.x = ha; hv.y = hb;
    __half2 lv;
    lv.x = __float2half_rn(a - __half2float(ha));
    lv.y = __float2half_rn(b - __half2float(hb));
    *reinterpret_cast<__half2*>(hi_p) = hv;
    *reinterpret_cast<__half2*>(lo_p) = lv;
}

// ============================ conversion kernels =============================
// A-side: f32 [M][1024] -> fp16 [M][2048], per 32-chunk interleave [hi32|lo32]
__global__ __launch_bounds__(256) void convert_a_kernel(
    const float* __restrict__ src, __half* __restrict__ dst, int total)
{
    int i = blockIdx.x * blockDim.x + threadIdx.x;
    if (i >= total) return;
    int m = i >> 10, k = i & 1023;
    float x = src[i];
    __half hi = __float2half_rn(x);
    __half lo = __float2half_rn(x - __half2float(hi));
    size_t o = (size_t)m * KP2 + (size_t)((k >> 5) * 64 + (k & 31));
    dst[o] = hi; dst[o + 32] = lo;
}

// W-side with transpose: W f32 [1024][N] -> fp16 [N][1024] (hi only)
__global__ __launch_bounds__(256) void convert_w_kernel(
    const float* __restrict__ W, __half* __restrict__ dst, int N)
{
    __shared__ float tile[32][33];
    int n0 = blockIdx.x * 32, k0 = blockIdx.y * 32;
    int tx = threadIdx.x, ty = threadIdx.y;             // (32, 8)
    #pragma unroll
    for (int j = 0; j < 32; j += 8)
        tile[ty + j][tx] = W[(size_t)(k0 + ty + j) * N + n0 + tx];
    __syncthreads();
    #pragma unroll
    for (int j = 0; j < 32; j += 8) {
        int n = n0 + ty + j, k = k0 + tx;
        dst[(size_t)n * D_MODEL + k] = __float2half_rn(tile[tx][ty + j]);
    }
}

// ============================ HMMA fp16 GEMM =================================
// C[M,N] = (Ah+Al)[M,1024] @ Bh[N,1024]^T + bias[N]; A interleaved [hi32|lo32].
#define NSTAGES 3
#define NCHUNK2 32                   // 32 chunks of 32 original k
#define STAGE_BYTES 24576            // A 16KB + B 8KB
#define GEMM_SMEM (NSTAGES * STAGE_BYTES)

template<int MODE>
__global__ __launch_bounds__(256, 2) void gemm_hmma_kernel(
    const __half* __restrict__ A, const __half* __restrict__ B,
    const float* __restrict__ bias, float* __restrict__ C,
    __half* __restrict__ Chi, __half* __restrict__ Clo, int N)
{
    extern __shared__ char smem[];
    const uint32_t sb = smem_u32(smem);
    const int tid  = threadIdx.x;
    const int wid  = tid >> 5;
    const int lane = tid & 31;
    const int wm   = wid & 1;
    const int wn   = wid >> 1;
    const int m0   = blockIdx.y * 128;
    const int n0   = blockIdx.x * 128;

    float acc[4][4][4];
    #pragma unroll
    for (int i = 0; i < 4; ++i)
        #pragma unroll
        for (int j = 0; j < 4; ++j)
            #pragma unroll
            for (int r = 0; r < 4; ++r) acc[i][j][r] = 0.f;

    const __half* Ab = A + (size_t)m0 * KP2;
    const __half* Bb = B + (size_t)n0 * D_MODEL;

    auto load_chunk = [&](int c) {
        int s = c % NSTAGES;
        uint32_t sa = sb + s * STAGE_BYTES;
        uint32_t sB = sa + 16384;
        // A: 128 rows x 128B ([hi32|lo32] fp16), SW128
        size_t ka = (size_t)c * 64;
        #pragma unroll
        for (int t = 0; t < 4; ++t) {
            int id = tid + t * 256;
            int r = id >> 3, c16 = id & 7;
            uint32_t soff = SW128(r * 128 + c16 * 16);
            cp16(sa + soff, Ab + (size_t)r * KP2 + ka + c16 * 8);
        }
        // B: 128 rows x 64B (32 fp16 hi), SW64
        size_t kb = (size_t)c * 32;
        #pragma unroll
        for (int t = 0; t < 2; ++t) {
            int id = tid + t * 256;
            int r = id >> 2, c16 = id & 3;
            uint32_t soff = SW64(r * 64 + c16 * 16);
            cp16(sB + soff, Bb + (size_t)r * D_MODEL + kb + c16 * 8);
        }
        CP_COMMIT();
    };

    const int a_row = wm * 64 + (lane & 15);
    const int a_kb  = (lane >> 4) * 16;
    const int b_row = wn * 32 + (lane & 7);
    const int b_kb  = ((lane >> 3) & 1) * 16;

    load_chunk(0);
    load_chunk(1);

    for (int c = 0; c < NCHUNK2; ++c) {
        if (c == NCHUNK2 - 1) { CP_WAIT(0); } else { CP_WAIT(1); }
        __syncthreads();
        if (c + 2 < NCHUNK2) load_chunk(c + 2);

        int s = c % NSTAGES;
        uint32_t sa = sb + s * STAGE_BYTES;
        uint32_t sB = sa + 16384;

        #pragma unroll
        for (int j = 0; j < 2; ++j) {          // k16 group within chunk
            uint32_t ahf[4][4], alf[4][4];
            #pragma unroll
            for (int mt = 0; mt < 4; ++mt) {
                uint32_t base = (uint32_t)((a_row + mt * 16) * 128 + j * 32 + a_kb);
                ldmx4(ahf[mt], sa + SW128(base));
                ldmx4(alf[mt], sa + SW128(base + 64));
            }
            #pragma unroll
            for (int nt = 0; nt < 4; ++nt) {
                uint32_t bh[2];
                uint32_t base = (uint32_t)((b_row + nt * 8) * 64 + j * 32 + b_kb);
                ldmx2(bh, sB + SW64(base));
                #pragma unroll
                for (int mt = 0; mt < 4; ++mt) mma16816(acc[mt][nt], ahf[mt], bh);
                #pragma unroll
                for (int mt = 0; mt < 4; ++mt) mma16816(acc[mt][nt], alf[mt], bh);
            }
        }
    }

    const int er = lane >> 2;
    const int ec = (lane & 3) * 2;
    #pragma unroll
    for (int mt = 0; mt < 4; ++mt) {
        #pragma unroll
        for (int nt = 0; nt < 4; ++nt) {
            int col = n0 + wn * 32 + nt * 8 + ec;
            float bx = bias[col], by = bias[col + 1];
            size_t r0 = (size_t)(m0 + wm * 64 + mt * 16 + er);
            float v00 = acc[mt][nt][0] + bx, v01 = acc[mt][nt][1] + by;
            float v10 = acc[mt][nt][2] + bx, v11 = acc[mt][nt][3] + by;
            if (MODE == 0) {
                float2 a0 = { v00, v01 }, a1 = { v10, v11 };
                *(float2*)&C[r0 * N + col]       = a0;
                *(float2*)&C[(r0 + 8) * N + col] = a1;
            } else {
                store_hilo2h(&Chi[r0 * N + col], &Clo[r0 * N + col], v00, v01);
                store_hilo2h(&Chi[(r0 + 8) * N + col], &Clo[(r0 + 8) * N + col], v10, v11);
            }
        }
    }
}

// ============================ HMMA flash attention (split-KV warps) ==========
// 8 warps = 4 (Q, 32 rows) x 2 (KV half). Q fp16 hi+lo; K/V fp16 hi only.
#define ABQ 128
#define ABK 64
#define ATTN_SMEM (32768 + 2 * 16384)   // Qh+Ql | 2 stages x (Kh,Vh)
#define OB_STRIDE 66
#define MS_OFF (128 * OB_STRIDE)
#define LS_OFF (MS_OFF + 128)

__global__ __launch_bounds__(256, 1) void attn_hmma_kernel(
    const __half* __restrict__ qkh, const __half* __restrict__ qkl,
    __half* __restrict__ ctxA)
{
    extern __shared__ char smem[];
    const uint32_t sb = smem_u32(smem);
    const uint32_t QH = 0, QL = 16384, STG = 32768;

    const int tid = threadIdx.x, wid = tid >> 5, lane = tid & 31;
    const int wq = wid >> 1;
    const int wk = wid & 1;
    const int qt = (int)gridDim.x - 1 - (int)blockIdx.x;
    const int h = blockIdx.y, b = blockIdx.z;
    const int q0 = qt * ABQ;
    const size_t rowbase = (size_t)b * SEQ;
    const int qcol = h * 64, kcol = 1024 + h * 64, vcol = 2048 + h * 64;

    #pragma unroll
    for (int t = 0; t < 4; ++t) {
        int id = tid + t * 256;
        int r = id >> 3, c = id & 7;
        uint32_t so = SW128(r * 128 + c * 16);
        size_t grow = (rowbase + q0 + r) * TRIPLE + qcol + c * 8;
        cp16(sb + QH + so, qkh + grow);
        cp16(sb + QL + so, qkl + grow);
    }
    CP_COMMIT();

    const int T = (q0 + ABQ) / ABK;

    auto load_kv = [&](int t) {
        uint32_t st = sb + STG + (uint32_t)(t & 1) * 16384;
        int k0 = t * ABK;
        #pragma unroll
        for (int i = 0; i < 2; ++i) {
            int id = tid + i * 256;              // 0..511
            int r = id >> 3, c = id & 7;         // r 0..63
            uint32_t so = SW128(r * 128 + c * 16);
            size_t grow = (rowbase + k0 + r) * TRIPLE;
            cp16(st + 0    + so, qkh + grow + kcol + c * 8);
            cp16(st + 8192 + so, qkh + grow + vcol + c * 8);
        }
        CP_COMMIT();
    };
    load_kv(0);
    CP_WAIT(0);
    __syncthreads();

    uint32_t qhf[2][4][4], qlf[2][4][4];
    {
        int arow = wq * 32 + (lane & 15);
        int akb = (lane >> 4) * 16;
        #pragma unroll
        for (int mt = 0; mt < 2; ++mt)
            #pragma unroll
            for (int ks = 0; ks < 4; ++ks) {
                uint32_t off = (uint32_t)((arow + mt * 16) * 128 + ks * 32 + akb);
                ldmx4(qhf[mt][ks], sb + QH + SW128(off));
                ldmx4(qlf[mt][ks], sb + QL + SW128(off));
            }
    }

    // m init = 0: fully-masked first chunk (upper-KV warp) -> p = exp(-1.25e8) = 0
    float m_run[2][2] = {{0.f, 0.f}, {0.f, 0.f}};
    float l_run[2][2] = {{0.f, 0.f}, {0.f, 0.f}};
    float o_acc[2][8][4];
    #pragma unroll
    for (int mt = 0; mt < 2; ++mt)
        #pragma unroll
        for (int nt = 0; nt < 8; ++nt)
            #pragma unroll
            for (int r = 0; r < 4; ++r) o_acc[mt][nt][r] = 0.f;

    const int r0l = lane >> 2;
    const int ecol = (lane & 3) * 2;
    const int brow = lane & 7;
    const int bkb  = ((lane >> 3) & 1) * 16;
    const int vrow = lane & 15;

    for (int t = 0; t < T; ++t) {
        __syncthreads();
        if (t + 1 < T) { load_kv(t + 1); CP_WAIT(1); } else { CP_WAIT(0); }
        __syncthreads();

        uint32_t st = sb + STG + (uint32_t)(t & 1) * 16384;

        // ---- S = (Qh+Ql) Kh^T on this warp's KV half ----
        float s_acc[2][4][4];
        #pragma unroll
        for (int mt = 0; mt < 2; ++mt)
            #pragma unroll
            for (int nt = 0; nt < 4; ++nt)
                #pragma unroll
                for (int r = 0; r < 4; ++r) s_acc[mt][nt][r] = 0.f;

        #pragma unroll
        for (int ks = 0; ks < 4; ++ks) {
            #pragma unroll
            for (int np = 0; np < 2; ++np) {
                uint32_t khf[2][2];
                #pragma unroll
                for (int q = 0; q < 2; ++q) {
                    int nt = np * 2 + q;
                    uint32_t off = (uint32_t)((wk * 32 + nt * 8 + brow) * 128 + ks * 32 + bkb);
                    ldmx2(khf[q], st + 0 + SW128(off));
                }
                #pragma unroll
                for (int q = 0; q < 2; ++q)
                    #pragma unroll
                    for (int mt = 0; mt < 2; ++mt)
                        mma16816(s_acc[mt][np * 2 + q], qhf[mt][ks], khf[q]);
                #pragma unroll
                for (int q = 0; q < 2; ++q)
                    #pragma unroll
                    for (int mt = 0; mt < 2; ++mt)
                        mma16816(s_acc[mt][np * 2 + q], qlf[mt][ks], khf[q]);
            }
        }

        // ---- mask (before scale) + scale + running max ----
        const int kb0 = t * ABK + wk * 32;
        float rmax[2][2] = {{-3.0e38f, -3.0e38f}, {-3.0e38f, -3.0e38f}};
        #pragma unroll
        for (int mt = 0; mt < 2; ++mt) {
            int qr0 = q0 + wq * 32 + mt * 16 + r0l;
            int qr1 = qr0 + 8;
            #pragma unroll
            for (int nt = 0; nt < 4; ++nt) {
                int kc = kb0 + nt * 8 + ecol;
                float v0 = (kc     > qr0) ? -1e9f : s_acc[mt][nt][0];
                float v1 = (kc + 1 > qr0) ? -1e9f : s_acc[mt][nt][1];
                float v2 = (kc     > qr1) ? -1e9f : s_acc[mt][nt][2];
                float v3 = (kc + 1 > qr1) ? -1e9f : s_acc[mt][nt][3];
                v0 *= 0.125f; v1 *= 0.125f; v2 *= 0.125f; v3 *= 0.125f;
                s_acc[mt][nt][0] = v0; s_acc[mt][nt][1] = v1;
                s_acc[mt][nt][2] = v2; s_acc[mt][nt][3] = v3;
                rmax[mt][0] = fmaxf(rmax[mt][0], fmaxf(v0, v1));
                rmax[mt][1] = fmaxf(rmax[mt][1], fmaxf(v2, v3));
            }
            #pragma unroll
            for (int off = 1; off <= 2; off <<= 1) {
                rmax[mt][0] = fmaxf(rmax[mt][0], __shfl_xor_sync(0xffffffffu, rmax[mt][0], off));
                rmax[mt][1] = fmaxf(rmax[mt][1], __shfl_xor_sync(0xffffffffu, rmax[mt][1], off));
            }
        }

        float mn[2][2], cr[2][2], ps[2][2];
        #pragma unroll
        for (int mt = 0; mt < 2; ++mt)
            #pragma unroll
            for (int hf = 0; hf < 2; ++hf) {
                mn[mt][hf] = fmaxf(m_run[mt][hf], rmax[mt][hf]);
                cr[mt][hf] = __expf(m_run[mt][hf] - mn[mt][hf]);
                ps[mt][hf] = 0.f;
            }

        // ---- exp + P fragment repack (fp16 hi/lo) ----
        uint32_t pha[2][2][4], pla[2][2][4];
        #pragma unroll
        for (int mt = 0; mt < 2; ++mt) {
            #pragma unroll
            for (int j = 0; j < 2; ++j) {
                float p00 = __expf(s_acc[mt][2*j][0] - mn[mt][0]);
                float p01 = __expf(s_acc[mt][2*j][1] - mn[mt][0]);
                float p02 = __expf(s_acc[mt][2*j][2] - mn[mt][1]);
                float p03 = __expf(s_acc[mt][2*j][3] - mn[mt][1]);
                float p10 = __expf(s_acc[mt][2*j+1][0] - mn[mt][0]);
                float p11 = __expf(s_acc[mt][2*j+1][1] - mn[mt][0]);
                float p12 = __expf(s_acc[mt][2*j+1][2] - mn[mt][1]);
                float p13 = __expf(s_acc[mt][2*j+1][3] - mn[mt][1]);
                ps[mt][0] += p00 + p01 + p10 + p11;
                ps[mt][1] += p02 + p03 + p12 + p13;
                __half h00 = __float2half_rn(p00), h01 = __float2half_rn(p01);
                __half h02 = __float2half_rn(p02), h03 = __float2half_rn(p03);
                __half h10 = __float2half_rn(p10), h11 = __float2half_rn(p11);
                __half h12 = __float2half_rn(p12), h13 = __float2half_rn(p13);
                pha[mt][j][0] = packh2(__half2float(h00), __half2float(h01));
                pha[mt][j][1] = packh2(__half2float(h02), __half2float(h03));
                pha[mt][j][2] = packh2(__half2float(h10), __half2float(h11));
                pha[mt][j][3] = packh2(__half2float(h12), __half2float(h13));
                pla[mt][j][0] = packh2(p00 - __half2float(h00), p01 - __half2float(h01));
                pla[mt][j][1] = packh2(p02 - __half2float(h02), p03 - __half2float(h03));
                pla[mt][j][2] = packh2(p10 - __half2float(h10), p11 - __half2float(h11));
                pla[mt][j][3] = packh2(p12 - __half2float(h12), p13 - __half2float(h13));
            }
        }
        #pragma unroll
        for (int mt = 0; mt < 2; ++mt)
            #pragma unroll
            for (int off = 1; off <= 2; off <<= 1) {
                ps[mt][0] += __shfl_xor_sync(0xffffffffu, ps[mt][0], off);
                ps[mt][1] += __shfl_xor_sync(0xffffffffu, ps[mt][1], off);
            }
        #pragma unroll
        for (int mt = 0; mt < 2; ++mt)
            #pragma unroll
            for (int hf = 0; hf < 2; ++hf) {
                l_run[mt][hf] = l_run[mt][hf] * cr[mt][hf] + ps[mt][hf];
                m_run[mt][hf] = mn[mt][hf];
            }
        #pragma unroll
        for (int mt = 0; mt < 2; ++mt)
            #pragma unroll
            for (int nt = 0; nt < 8; ++nt) {
                o_acc[mt][nt][0] *= cr[mt][0]; o_acc[mt][nt][1] *= cr[mt][0];
                o_acc[mt][nt][2] *= cr[mt][1]; o_acc[mt][nt][3] *= cr[mt][1];
            }

        // ---- O += (Ph+Pl) Vh on this warp's KV half ----
        #pragma unroll
        for (int j = 0; j < 2; ++j) {
            #pragma unroll
            for (int np = 0; np < 4; ++np) {
                uint32_t vhf[2][2];
                #pragma unroll
                for (int q = 0; q < 2; ++q) {
                    int nt = np * 2 + q;
                    uint32_t off = (uint32_t)((wk * 32 + j * 16 + vrow) * 128 + nt * 16);
                    ldmx2t(vhf[q], st + 8192 + SW128(off));
                }
                #pragma unroll
                for (int q = 0; q < 2; ++q)
                    #pragma unroll
                    for (int mt = 0; mt < 2; ++mt)
                        mma16816(o_acc[mt][np * 2 + q], pha[mt][j], vhf[q]);
                #pragma unroll
                for (int q = 0; q < 2; ++q)
                    #pragma unroll
                    for (int mt = 0; mt < 2; ++mt)
                        mma16816(o_acc[mt][np * 2 + q], pla[mt][j], vhf[q]);
            }
        }
    }

    // ---- cross-warp merge (wk=1 -> smem, wk=0 merges + writes) ----
    float* smf = reinterpret_cast<float*>(smem);
    __syncthreads();
    if (wk == 1) {
        #pragma unroll
        for (int mt = 0; mt < 2; ++mt) {
            int rA = wq * 32 + mt * 16 + r0l;
            #pragma unroll
            for (int nt = 0; nt < 8; ++nt) {
                int d = nt * 8 + ecol;
                smf[rA * OB_STRIDE + d]     = o_acc[mt][nt][0];
                smf[rA * OB_STRIDE + d + 1] = o_acc[mt][nt][1];
                smf[(rA + 8) * OB_STRIDE + d]     = o_acc[mt][nt][2];
                smf[(rA + 8) * OB_STRIDE + d + 1] = o_acc[mt][nt][3];
            }
            if ((lane & 3) == 0) {
                smf[MS_OFF + rA]     = m_run[mt][0];
                smf[LS_OFF + rA]     = l_run[mt][0];
                smf[MS_OFF + rA + 8] = m_run[mt][1];
                smf[LS_OFF + rA + 8] = l_run[mt][1];
            }
        }
    }
    __syncthreads();
    if (wk == 0) {
        #pragma unroll
        for (int mt = 0; mt < 2; ++mt) {
            int rA = wq * 32 + mt * 16 + r0l;
            float m1a = smf[MS_OFF + rA],     l1a = smf[LS_OFF + rA];
            float m1b = smf[MS_OFF + rA + 8], l1b = smf[LS_OFF + rA + 8];
            float mA = fmaxf(m_run[mt][0], m1a);
            float c0a = __expf(m_run[mt][0] - mA), c1a = __expf(m1a - mA);
            float invA = 1.0f / (l_run[mt][0] * c0a + l1a * c1a);
            float mB = fmaxf(m_run[mt][1], m1b);
            float c0b = __expf(m_run[mt][1] - mB), c1b = __expf(m1b - mB);
            float invB = 1.0f / (l_run[mt][1] * c0b + l1b * c1b);
            size_t tokA = rowbase + (size_t)q0 + rA;
            #pragma unroll
            for (int nt = 0; nt < 8; ++nt) {
                int d = nt * 8 + ecol;
                float vA0 = (o_acc[mt][nt][0] * c0a + smf[rA * OB_STRIDE + d]     * c1a) * invA;
                float vA1 = (o_acc[mt][nt][1] * c0a + smf[rA * OB_STRIDE + d + 1] * c1a) * invA;
                float vB0 = (o_acc[mt][nt][2] * c0b + smf[(rA + 8) * OB_STRIDE + d]     * c1b) * invB;
                float vB1 = (o_acc[mt][nt][3] * c0b + smf[(rA + 8) * OB_STRIDE + d + 1] * c1b) * invB;
                // write ctx in interleaved A'' fp16 layout
                int dg = h * 64 + d;
                size_t colhi = (size_t)((dg >> 5) * 64 + (dg & 31));
                store_hilo2h(&ctxA[tokA * KP2 + colhi],       &ctxA[tokA * KP2 + colhi + 32],       vA0, vA1);
                store_hilo2h(&ctxA[(tokA + 8) * KP2 + colhi], &ctxA[(tokA + 8) * KP2 + colhi + 32], vB0, vB1);
            }
        }
    }
}

// ============================ launch =========================================
extern "C" void kernel_launch(void* const* d_in, const int* in_sizes, int n_in,
                              void* d_out, int out_size)
{
    (void)in_sizes; (void)n_in; (void)out_size;
    const float* x      = (const float*)d_in[0];
    const float* W_qkv  = (const float*)d_in[1];
    const float* b_qkv  = (const float*)d_in[2];
    const float* W_proj = (const float*)d_in[3];
    const float* b_proj = (const float*)d_in[4];
    float* out = (float*)d_out;

    __half *a_buf, *wq_buf, *wp_buf, *qh_buf, *ql_buf;
    cudaGetSymbolAddress((void**)&a_buf, g_a);
    cudaGetSymbolAddress((void**)&wq_buf, g_wq);
    cudaGetSymbolAddress((void**)&wp_buf, g_wp);
    cudaGetSymbolAddress((void**)&qh_buf, g_qh);
    cudaGetSymbolAddress((void**)&ql_buf, g_ql);

    static bool attr_set = false;
    if (!attr_set) {
        cudaFuncSetAttribute(gemm_hmma_kernel<0>, cudaFuncAttributeMaxDynamicSharedMemorySize, GEMM_SMEM);
        cudaFuncSetAttribute(gemm_hmma_kernel<1>, cudaFuncAttributeMaxDynamicSharedMemorySize, GEMM_SMEM);
        cudaFuncSetAttribute(attn_hmma_kernel, cudaFuncAttributeMaxDynamicSharedMemorySize, ATTN_SMEM);
        attr_set = true;
    }

    convert_a_kernel<<<(NTOK * D_MODEL + 255) / 256, 256>>>(x, a_buf, NTOK * D_MODEL);
    {
        dim3 grid(TRIPLE / 32, D_MODEL / 32);
        convert_w_kernel<<<grid, dim3(32, 8)>>>(W_qkv, wq_buf, TRIPLE);
    }
    {
        dim3 grid(D_MODEL / 32, D_MODEL / 32);
        convert_w_kernel<<<grid, dim3(32, 8)>>>(W_proj, wp_buf, D_MODEL);
    }

    {
        dim3 grid(TRIPLE / 128, NTOK / 128);
        gemm_hmma_kernel<1><<<grid, 256, GEMM_SMEM>>>(a_buf, wq_buf, b_qkv, nullptr, qh_buf, ql_buf, TRIPLE);
    }

    {
        dim3 grid(SEQ / ABQ, N_HEADS, BATCH);
        attn_hmma_kernel<<<grid, 256, ATTN_SMEM>>>(qh_buf, ql_buf, a_buf);
    }

    {
        dim3 grid(D_MODEL / 128, NTOK / 128);
        gemm_hmma_kernel<0><<<grid, 256, GEMM_SMEM>>>(a_buf, wp_buf, b_proj, out, nullptr, nullptr, D_MODEL);
    }
}

// round 8
// speedup vs baseline: 2.2979x; 1.7171x over previous
#include <cuda_runtime.h>
#include <cuda_fp16.h>
#include <math.h>
#include <stdint.h>

// Problem constants
#define D_MODEL 1024
#define N_HEADS 16
#define D_HEAD  64
#define SEQ     2048
#define BATCH   2
#define NTOK    (BATCH * SEQ)        // 4096
#define TRIPLE  (3 * D_MODEL)        // 3072

// Scratch (allocation-free rule: __device__ globals)
__device__ __half g_a [(size_t)NTOK * D_MODEL];    // fp16 x, then ctx
__device__ __half g_wq[(size_t)TRIPLE * D_MODEL];  // W_qkv^T fp16
__device__ __half g_wp[(size_t)D_MODEL * D_MODEL]; // W_proj^T fp16
__device__ __half g_qh[(size_t)NTOK * TRIPLE];     // qkv fp16

// ============================ helpers ========================================
__device__ __forceinline__ uint32_t smem_u32(const void* p) {
    uint32_t a;
    asm("{ .reg .u64 t; cvta.to.shared.u64 t, %1; cvt.u32.u64 %0, t; }" : "=r"(a) : "l"(p));
    return a;
}
#define SW128(off) ((off) ^ (((off) >> 3) & 0x70))

__device__ __forceinline__ void cp16(uint32_t dst, const void* src) {
    asm volatile("cp.async.cg.shared.global [%0], [%1], 16;" :: "r"(dst), "l"(src) : "memory");
}
#define CP_COMMIT() asm volatile("cp.async.commit_group;" ::: "memory")
#define CP_WAIT(n)  asm volatile("cp.async.wait_group %0;" :: "n"(n) : "memory")

__device__ __forceinline__ void ldmx4(uint32_t* r, uint32_t addr) {
    asm volatile("ldmatrix.sync.aligned.m8n8.x4.shared.b16 {%0,%1,%2,%3}, [%4];"
                 : "=r"(r[0]), "=r"(r[1]), "=r"(r[2]), "=r"(r[3]) : "r"(addr));
}
__device__ __forceinline__ void ldmx2(uint32_t* r, uint32_t addr) {
    asm volatile("ldmatrix.sync.aligned.m8n8.x2.shared.b16 {%0,%1}, [%2];"
                 : "=r"(r[0]), "=r"(r[1]) : "r"(addr));
}
__device__ __forceinline__ void ldmx2t(uint32_t* r, uint32_t addr) {
    asm volatile("ldmatrix.sync.aligned.m8n8.x2.trans.shared.b16 {%0,%1}, [%2];"
                 : "=r"(r[0]), "=r"(r[1]) : "r"(addr));
}
__device__ __forceinline__ void mma16816(float* d, const uint32_t* a, const uint32_t* b) {
    asm volatile(
        "mma.sync.aligned.m16n8k16.row.col.f32.f16.f16.f32 "
        "{%0,%1,%2,%3}, {%4,%5,%6,%7}, {%8,%9}, {%0,%1,%2,%3};"
        : "+f"(d[0]), "+f"(d[1]), "+f"(d[2]), "+f"(d[3])
        : "r"(a[0]), "r"(a[1]), "r"(a[2]), "r"(a[3]), "r"(b[0]), "r"(b[1]));
}
__device__ __forceinline__ uint32_t packh2(float a, float b) {
    __half2 t = __floats2half2_rn(a, b);
    return *reinterpret_cast<uint32_t*>(&t);
}

// ============================ conversion kernels =============================
// x f32 [M][1024] -> fp16 [M][1024]
__global__ __launch_bounds__(256) void convert_a_kernel(
    const float* __restrict__ src, __half* __restrict__ dst, int total4)
{
    int i = blockIdx.x * blockDim.x + threadIdx.x;
    if (i >= total4) return;
    float4 v = *(const float4*)&src[i * 4];
    __half2 h0 = __floats2half2_rn(v.x, v.y);
    __half2 h1 = __floats2half2_rn(v.z, v.w);
    *(__half2*)&dst[i * 4]     = h0;
    *(__half2*)&dst[i * 4 + 2] = h1;
}

// W f32 [1024][N] -> fp16 [N][1024] (transpose)
__global__ __launch_bounds__(256) void convert_w_kernel(
    const float* __restrict__ W, __half* __restrict__ dst, int N)
{
    __shared__ float tile[32][33];
    int n0 = blockIdx.x * 32, k0 = blockIdx.y * 32;
    int tx = threadIdx.x, ty = threadIdx.y;             // (32, 8)
    #pragma unroll
    for (int j = 0; j < 32; j += 8)
        tile[ty + j][tx] = W[(size_t)(k0 + ty + j) * N + n0 + tx];
    __syncthreads();
    #pragma unroll
    for (int j = 0; j < 32; j += 8) {
        int n = n0 + ty + j, k = k0 + tx;
        dst[(size_t)n * D_MODEL + k] = __float2half_rn(tile[tx][ty + j]);
    }
}

// ============================ HMMA fp16 GEMM =================================
// C[M,N] = A[M,1024] @ B[N,1024]^T + bias[N]; plain fp16 operands, fp32 acc.
#define NSTAGES 3
#define NCHUNK 16                    // 16 chunks of K=64 (128B rows)
#define STAGE_BYTES 32768            // A 16KB + B 16KB
#define GEMM_SMEM (NSTAGES * STAGE_BYTES)

template<int MODE>
__global__ __launch_bounds__(256, 2) void gemm_hmma_kernel(
    const __half* __restrict__ A, const __half* __restrict__ B,
    const float* __restrict__ bias, float* __restrict__ C,
    __half* __restrict__ Ch, int N)
{
    extern __shared__ char smem[];
    const uint32_t sb = smem_u32(smem);
    const int tid  = threadIdx.x;
    const int wid  = tid >> 5;
    const int lane = tid & 31;
    const int wm   = wid & 1;
    const int wn   = wid >> 1;
    const int m0   = blockIdx.y * 128;
    const int n0   = blockIdx.x * 128;

    float acc[4][4][4];
    #pragma unroll
    for (int i = 0; i < 4; ++i)
        #pragma unroll
        for (int j = 0; j < 4; ++j)
            #pragma unroll
            for (int r = 0; r < 4; ++r) acc[i][j][r] = 0.f;

    const __half* Ab = A + (size_t)m0 * D_MODEL;
    const __half* Bb = B + (size_t)n0 * D_MODEL;

    auto load_chunk = [&](int c) {
        int s = c % NSTAGES;
        uint32_t sa = sb + s * STAGE_BYTES;
        uint32_t sB = sa + 16384;
        size_t koff = (size_t)c * 64;
        #pragma unroll
        for (int t = 0; t < 4; ++t) {
            int id = tid + t * 256;
            int r = id >> 3, c16 = id & 7;
            uint32_t soff = SW128(r * 128 + c16 * 16);
            cp16(sa + soff, Ab + (size_t)r * D_MODEL + koff + c16 * 8);
            cp16(sB + soff, Bb + (size_t)r * D_MODEL + koff + c16 * 8);
        }
        CP_COMMIT();
    };

    const int a_row = wm * 64 + (lane & 15);
    const int a_kb  = (lane >> 4) * 16;
    const int b_row = wn * 32 + (lane & 7);
    const int b_kb  = ((lane >> 3) & 1) * 16;

    load_chunk(0);
    load_chunk(1);

    for (int c = 0; c < NCHUNK; ++c) {
        if (c == NCHUNK - 1) { CP_WAIT(0); } else { CP_WAIT(1); }
        __syncthreads();
        if (c + 2 < NCHUNK) load_chunk(c + 2);

        int s = c % NSTAGES;
        uint32_t sa = sb + s * STAGE_BYTES;
        uint32_t sB = sa + 16384;

        #pragma unroll
        for (int j = 0; j < 4; ++j) {          // 4 k16 groups per chunk
            uint32_t ahf[4][4];
            #pragma unroll
            for (int mt = 0; mt < 4; ++mt) {
                uint32_t base = (uint32_t)((a_row + mt * 16) * 128 + j * 32 + a_kb);
                ldmx4(ahf[mt], sa + SW128(base));
            }
            #pragma unroll
            for (int nt = 0; nt < 4; ++nt) {
                uint32_t bh[2];
                uint32_t base = (uint32_t)((b_row + nt * 8) * 128 + j * 32 + b_kb);
                ldmx2(bh, sB + SW128(base));
                #pragma unroll
                for (int mt = 0; mt < 4; ++mt) mma16816(acc[mt][nt], ahf[mt], bh);
            }
        }
    }

    const int er = lane >> 2;
    const int ec = (lane & 3) * 2;
    #pragma unroll
    for (int mt = 0; mt < 4; ++mt) {
        #pragma unroll
        for (int nt = 0; nt < 4; ++nt) {
            int col = n0 + wn * 32 + nt * 8 + ec;
            float bx = bias[col], by = bias[col + 1];
            size_t r0 = (size_t)(m0 + wm * 64 + mt * 16 + er);
            float v00 = acc[mt][nt][0] + bx, v01 = acc[mt][nt][1] + by;
            float v10 = acc[mt][nt][2] + bx, v11 = acc[mt][nt][3] + by;
            if (MODE == 0) {
                float2 a0 = { v00, v01 }, a1 = { v10, v11 };
                *(float2*)&C[r0 * N + col]       = a0;
                *(float2*)&C[(r0 + 8) * N + col] = a1;
            } else {
                __half2 h0 = __floats2half2_rn(v00, v01);
                __half2 h1 = __floats2half2_rn(v10, v11);
                *(__half2*)&Ch[r0 * N + col]       = h0;
                *(__half2*)&Ch[(r0 + 8) * N + col] = h1;
            }
        }
    }
}

// ============================ HMMA flash attention (split-KV warps) ==========
// 8 warps = 4 (Q, 32 rows) x 2 (KV half). Plain fp16 Q/K/V/P, fp32 acc.
#define ABQ 128
#define ABK 64
#define ATTN_SMEM (16384 + 2 * 16384)   // Q | 2 stages x (K 8KB, V 8KB)
#define OB_STRIDE 66
#define MS_OFF (128 * OB_STRIDE)
#define LS_OFF (MS_OFF + 128)

__global__ __launch_bounds__(256, 1) void attn_hmma_kernel(
    const __half* __restrict__ qkv, __half* __restrict__ ctxA)
{
    extern __shared__ char smem[];
    const uint32_t sb = smem_u32(smem);
    const uint32_t QH = 0, STG = 16384;

    const int tid = threadIdx.x, wid = tid >> 5, lane = tid & 31;
    const int wq = wid >> 1;
    const int wk = wid & 1;
    const int qt = (int)gridDim.x - 1 - (int)blockIdx.x;   // big tiles first
    const int h = blockIdx.y, b = blockIdx.z;
    const int q0 = qt * ABQ;
    const size_t rowbase = (size_t)b * SEQ;
    const int qcol = h * 64, kcol = 1024 + h * 64, vcol = 2048 + h * 64;

    #pragma unroll
    for (int t = 0; t < 4; ++t) {
        int id = tid + t * 256;                  // 0..1023
        int r = id >> 3, c = id & 7;
        uint32_t so = SW128(r * 128 + c * 16);
        cp16(sb + QH + so, qkv + (rowbase + q0 + r) * TRIPLE + qcol + c * 8);
    }
    CP_COMMIT();

    const int T = (q0 + ABQ) / ABK;

    auto load_kv = [&](int t) {
        uint32_t st = sb + STG + (uint32_t)(t & 1) * 16384;
        int k0 = t * ABK;
        #pragma unroll
        for (int i = 0; i < 2; ++i) {
            int id = tid + i * 256;              // 0..511
            int r = id >> 3, c = id & 7;         // r 0..63
            uint32_t so = SW128(r * 128 + c * 16);
            size_t grow = (rowbase + k0 + r) * TRIPLE;
            cp16(st + 0    + so, qkv + grow + kcol + c * 8);
            cp16(st + 8192 + so, qkv + grow + vcol + c * 8);
        }
        CP_COMMIT();
    };
    load_kv(0);
    CP_WAIT(0);
    __syncthreads();

    uint32_t qhf[2][4][4];
    {
        int arow = wq * 32 + (lane & 15);
        int akb = (lane >> 4) * 16;
        #pragma unroll
        for (int mt = 0; mt < 2; ++mt)
            #pragma unroll
            for (int ks = 0; ks < 4; ++ks) {
                uint32_t off = (uint32_t)((arow + mt * 16) * 128 + ks * 32 + akb);
                ldmx4(qhf[mt][ks], sb + QH + SW128(off));
            }
    }

    // m init = 0: fully-masked first chunk (upper-KV warp) -> p = exp(-1.25e8) = 0
    float m_run[2][2] = {{0.f, 0.f}, {0.f, 0.f}};
    float l_run[2][2] = {{0.f, 0.f}, {0.f, 0.f}};
    float o_acc[2][8][4];
    #pragma unroll
    for (int mt = 0; mt < 2; ++mt)
        #pragma unroll
        for (int nt = 0; nt < 8; ++nt)
            #pragma unroll
            for (int r = 0; r < 4; ++r) o_acc[mt][nt][r] = 0.f;

    const int r0l = lane >> 2;
    const int ecol = (lane & 3) * 2;
    const int brow = lane & 7;
    const int bkb  = ((lane >> 3) & 1) * 16;
    const int vrow = lane & 15;

    for (int t = 0; t < T; ++t) {
        __syncthreads();
        if (t + 1 < T) { load_kv(t + 1); CP_WAIT(1); } else { CP_WAIT(0); }
        __syncthreads();

        uint32_t st = sb + STG + (uint32_t)(t & 1) * 16384;

        // ---- S = Q K^T on this warp's KV half ----
        float s_acc[2][4][4];
        #pragma unroll
        for (int mt = 0; mt < 2; ++mt)
            #pragma unroll
            for (int nt = 0; nt < 4; ++nt)
                #pragma unroll
                for (int r = 0; r < 4; ++r) s_acc[mt][nt][r] = 0.f;

        #pragma unroll
        for (int ks = 0; ks < 4; ++ks) {
            #pragma unroll
            for (int np = 0; np < 2; ++np) {
                uint32_t khf[2][2];
                #pragma unroll
                for (int q = 0; q < 2; ++q) {
                    int nt = np * 2 + q;
                    uint32_t off = (uint32_t)((wk * 32 + nt * 8 + brow) * 128 + ks * 32 + bkb);
                    ldmx2(khf[q], st + 0 + SW128(off));
                }
                #pragma unroll
                for (int q = 0; q < 2; ++q)
                    #pragma unroll
                    for (int mt = 0; mt < 2; ++mt)
                        mma16816(s_acc[mt][np * 2 + q], qhf[mt][ks], khf[q]);
            }
        }

        // ---- mask (before scale) + scale + running max ----
        const int kb0 = t * ABK + wk * 32;
        float rmax[2][2] = {{-3.0e38f, -3.0e38f}, {-3.0e38f, -3.0e38f}};
        #pragma unroll
        for (int mt = 0; mt < 2; ++mt) {
            int qr0 = q0 + wq * 32 + mt * 16 + r0l;
            int qr1 = qr0 + 8;
            #pragma unroll
            for (int nt = 0; nt < 4; ++nt) {
                int kc = kb0 + nt * 8 + ecol;
                float v0 = (kc     > qr0) ? -1e9f : s_acc[mt][nt][0];
                float v1 = (kc + 1 > qr0) ? -1e9f : s_acc[mt][nt][1];
                float v2 = (kc     > qr1) ? -1e9f : s_acc[mt][nt][2];
                float v3 = (kc + 1 > qr1) ? -1e9f : s_acc[mt][nt][3];
                v0 *= 0.125f; v1 *= 0.125f; v2 *= 0.125f; v3 *= 0.125f;
                s_acc[mt][nt][0] = v0; s_acc[mt][nt][1] = v1;
                s_acc[mt][nt][2] = v2; s_acc[mt][nt][3] = v3;
                rmax[mt][0] = fmaxf(rmax[mt][0], fmaxf(v0, v1));
                rmax[mt][1] = fmaxf(rmax[mt][1], fmaxf(v2, v3));
            }
            #pragma unroll
            for (int off = 1; off <= 2; off <<= 1) {
                rmax[mt][0] = fmaxf(rmax[mt][0], __shfl_xor_sync(0xffffffffu, rmax[mt][0], off));
                rmax[mt][1] = fmaxf(rmax[mt][1], __shfl_xor_sync(0xffffffffu, rmax[mt][1], off));
            }
        }

        float mn[2][2], cr[2][2], ps[2][2];
        #pragma unroll
        for (int mt = 0; mt < 2; ++mt)
            #pragma unroll
            for (int hf = 0; hf < 2; ++hf) {
                mn[mt][hf] = fmaxf(m_run[mt][hf], rmax[mt][hf]);
                cr[mt][hf] = __expf(m_run[mt][hf] - mn[mt][hf]);
                ps[mt][hf] = 0.f;
            }

        // ---- exp + P fragment pack (fp16) ----
        uint32_t pha[2][2][4];
        #pragma unroll
        for (int mt = 0; mt < 2; ++mt) {
            #pragma unroll
            for (int j = 0; j < 2; ++j) {
                float p00 = __expf(s_acc[mt][2*j][0] - mn[mt][0]);
                float p01 = __expf(s_acc[mt][2*j][1] - mn[mt][0]);
                float p02 = __expf(s_acc[mt][2*j][2] - mn[mt][1]);
                float p03 = __expf(s_acc[mt][2*j][3] - mn[mt][1]);
                float p10 = __expf(s_acc[mt][2*j+1][0] - mn[mt][0]);
                float p11 = __expf(s_acc[mt][2*j+1][1] - mn[mt][0]);
                float p12 = __expf(s_acc[mt][2*j+1][2] - mn[mt][1]);
                float p13 = __expf(s_acc[mt][2*j+1][3] - mn[mt][1]);
                ps[mt][0] += p00 + p01 + p10 + p11;
                ps[mt][1] += p02 + p03 + p12 + p13;
                pha[mt][j][0] = packh2(p00, p01);
                pha[mt][j][1] = packh2(p02, p03);
                pha[mt][j][2] = packh2(p10, p11);
                pha[mt][j][3] = packh2(p12, p13);
            }
        }
        #pragma unroll
        for (int mt = 0; mt < 2; ++mt)
            #pragma unroll
            for (int off = 1; off <= 2; off <<= 1) {
                ps[mt][0] += __shfl_xor_sync(0xffffffffu, ps[mt][0], off);
                ps[mt][1] += __shfl_xor_sync(0xffffffffu, ps[mt][1], off);
            }
        #pragma unroll
        for (int mt = 0; mt < 2; ++mt)
            #pragma unroll
            for (int hf = 0; hf < 2; ++hf) {
                l_run[mt][hf] = l_run[mt][hf] * cr[mt][hf] + ps[mt][hf];
                m_run[mt][hf] = mn[mt][hf];
            }
        #pragma unroll
        for (int mt = 0; mt < 2; ++mt)
            #pragma unroll
            for (int nt = 0; nt < 8; ++nt) {
                o_acc[mt][nt][0] *= cr[mt][0]; o_acc[mt][nt][1] *= cr[mt][0];
                o_acc[mt][nt][2] *= cr[mt][1]; o_acc[mt][nt][3] *= cr[mt][1];
            }

        // ---- O += P V on this warp's KV half ----
        #pragma unroll
        for (int j = 0; j < 2; ++j) {
            #pragma unroll
            for (int np = 0; np < 4; ++np) {
                uint32_t vhf[2][2];
                #pragma unroll
                for (int q = 0; q < 2; ++q) {
                    int nt = np * 2 + q;
                    uint32_t off = (uint32_t)((wk * 32 + j * 16 + vrow) * 128 + nt * 16);
                    ldmx2t(vhf[q], st + 8192 + SW128(off));
                }
                #pragma unroll
                for (int q = 0; q < 2; ++q)
                    #pragma unroll
                    for (int mt = 0; mt < 2; ++mt)
                        mma16816(o_acc[mt][np * 2 + q], pha[mt][j], vhf[q]);
            }
        }
    }

    // ---- cross-warp merge (wk=1 -> smem, wk=0 merges + writes) ----
    float* smf = reinterpret_cast<float*>(smem);
    __syncthreads();
    if (wk == 1) {
        #pragma unroll
        for (int mt = 0; mt < 2; ++mt) {
            int rA = wq * 32 + mt * 16 + r0l;
            #pragma unroll
            for (int nt = 0; nt < 8; ++nt) {
                int d = nt * 8 + ecol;
                smf[rA * OB_STRIDE + d]     = o_acc[mt][nt][0];
                smf[rA * OB_STRIDE + d + 1] = o_acc[mt][nt][1];
                smf[(rA + 8) * OB_STRIDE + d]     = o_acc[mt][nt][2];
                smf[(rA + 8) * OB_STRIDE + d + 1] = o_acc[mt][nt][3];
            }
            if ((lane & 3) == 0) {
                smf[MS_OFF + rA]     = m_run[mt][0];
                smf[LS_OFF + rA]     = l_run[mt][0];
                smf[MS_OFF + rA + 8] = m_run[mt][1];
                smf[LS_OFF + rA + 8] = l_run[mt][1];
            }
        }
    }
    __syncthreads();
    if (wk == 0) {
        #pragma unroll
        for (int mt = 0; mt < 2; ++mt) {
            int rA = wq * 32 + mt * 16 + r0l;
            float m1a = smf[MS_OFF + rA],     l1a = smf[LS_OFF + rA];
            float m1b = smf[MS_OFF + rA + 8], l1b = smf[LS_OFF + rA + 8];
            float mA = fmaxf(m_run[mt][0], m1a);
            float c0a = __expf(m_run[mt][0] - mA), c1a = __expf(m1a - mA);
            float invA = 1.0f / (l_run[mt][0] * c0a + l1a * c1a);
            float mB = fmaxf(m_run[mt][1], m1b);
            float c0b = __expf(m_run[mt][1] - mB), c1b = __expf(m1b - mB);
            float invB = 1.0f / (l_run[mt][1] * c0b + l1b * c1b);
            size_t tokA = rowbase + (size_t)q0 + rA;
            #pragma unroll
            for (int nt = 0; nt < 8; ++nt) {
                int d = nt * 8 + ecol;
                float vA0 = (o_acc[mt][nt][0] * c0a + smf[rA * OB_STRIDE + d]     * c1a) * invA;
                float vA1 = (o_acc[mt][nt][1] * c0a + smf[rA * OB_STRIDE + d + 1] * c1a) * invA;
                float vB0 = (o_acc[mt][nt][2] * c0b + smf[(rA + 8) * OB_STRIDE + d]     * c1b) * invB;
                float vB1 = (o_acc[mt][nt][3] * c0b + smf[(rA + 8) * OB_STRIDE + d + 1] * c1b) * invB;
                int gcol = h * 64 + d;
                *(__half2*)&ctxA[tokA * D_MODEL + gcol]       = __floats2half2_rn(vA0, vA1);
                *(__half2*)&ctxA[(tokA + 8) * D_MODEL + gcol] = __floats2half2_rn(vB0, vB1);
            }
        }
    }
}

// ============================ launch =========================================
extern "C" void kernel_launch(void* const* d_in, const int* in_sizes, int n_in,
                              void* d_out, int out_size)
{
    (void)in_sizes; (void)n_in; (void)out_size;
    const float* x      = (const float*)d_in[0];
    const float* W_qkv  = (const float*)d_in[1];
    const float* b_qkv  = (const float*)d_in[2];
    const float* W_proj = (const float*)d_in[3];
    const float* b_proj = (const float*)d_in[4];
    float* out = (float*)d_out;

    __half *a_buf, *wq_buf, *wp_buf, *qh_buf;
    cudaGetSymbolAddress((void**)&a_buf, g_a);
    cudaGetSymbolAddress((void**)&wq_buf, g_wq);
    cudaGetSymbolAddress((void**)&wp_buf, g_wp);
    cudaGetSymbolAddress((void**)&qh_buf, g_qh);

    static bool attr_set = false;
    if (!attr_set) {
        cudaFuncSetAttribute(gemm_hmma_kernel<0>, cudaFuncAttributeMaxDynamicSharedMemorySize, GEMM_SMEM);
        cudaFuncSetAttribute(gemm_hmma_kernel<1>, cudaFuncAttributeMaxDynamicSharedMemorySize, GEMM_SMEM);
        cudaFuncSetAttribute(attn_hmma_kernel, cudaFuncAttributeMaxDynamicSharedMemorySize, ATTN_SMEM);
        attr_set = true;
    }

    // 1) conversions to fp16
    convert_a_kernel<<<(NTOK * D_MODEL / 4 + 255) / 256, 256>>>(x, a_buf, NTOK * D_MODEL / 4);
    {
        dim3 grid(TRIPLE / 32, D_MODEL / 32);
        convert_w_kernel<<<grid, dim3(32, 8)>>>(W_qkv, wq_buf, TRIPLE);
    }
    {
        dim3 grid(D_MODEL / 32, D_MODEL / 32);
        convert_w_kernel<<<grid, dim3(32, 8)>>>(W_proj, wp_buf, D_MODEL);
    }

    // 2) QKV GEMM -> fp16 qkv
    {
        dim3 grid(TRIPLE / 128, NTOK / 128);
        gemm_hmma_kernel<1><<<grid, 256, GEMM_SMEM>>>(a_buf, wq_buf, b_qkv, nullptr, qh_buf, TRIPLE);
    }

    // 3) split-KV HMMA flash attention -> ctx fp16 (overwrites g_a)
    {
        dim3 grid(SEQ / ABQ, N_HEADS, BATCH);
        attn_hmma_kernel<<<grid, 256, ATTN_SMEM>>>(qh_buf, a_buf);
    }

    // 4) output projection (fp32 out + bias)
    {
        dim3 grid(D_MODEL / 128, NTOK / 128);
        gemm_hmma_kernel<0><<<grid, 256, GEMM_SMEM>>>(a_buf, wp_buf, b_proj, out, nullptr, D_MODEL);
    }
}